// round 10
// baseline (speedup 1.0000x reference)
#include <cuda_runtime.h>
#include <math.h>

#define BTCH 2
#define NTOK 6400
#define NBINS 50
#define BINSZ 128
#define DDIM 32
#define FDIM 256
#define NKEY 100

// output packing (floats): [bins_split | x_features_binned | dm | msk_f_binned]
#define O1 12800ULL
#define O2 3289600ULL
#define O3 55718400ULL

// fused-kernel block layout: [fill 400 | gather 200 | compute 1600]
// 100 tiles total (2 batches x 50 bins)
#define FILL_BLOCKS 400
#define GATH_BASE   400
#define GATH_BLOCKS 200
#define COMP_BASE   600
#define COMP_BLOCKS 1600
#define TOTAL_BLOCKS 2200

typedef unsigned long long ull;

__device__ int g_bin_idx[BTCH * NTOK];
__device__ int g_bins[BTCH * NTOK];

// fast elu: max(x,0) + (exp(min(x,0)) - 1);  exp(0)==1 exactly
__device__ __forceinline__ float eluf(float x) {
    return fmaxf(x, 0.f) + (__expf(fminf(x, 0.f)) - 1.f);
}

__device__ __forceinline__ ull pk2(float lo, float hi) {
    ull r;
    asm("mov.b64 %0, {%1, %2};" : "=l"(r) : "f"(lo), "f"(hi));
    return r;
}
__device__ __forceinline__ ull ffma2(ull a, ull b, ull c) {
    ull d;
    asm("fma.rn.f32x2 %0, %1, %2, %3;" : "=l"(d) : "l"(a), "l"(b), "l"(c));
    return d;
}
__device__ __forceinline__ float2 upk2(ull a) {
    float2 v;
    asm("mov.b64 {%0, %1}, %2;" : "=f"(v.x), "=f"(v.y) : "l"(a));
    return v;
}

// one k-step of a 32-wide o-packed dual-i accumulation
__device__ __forceinline__ void acc_step(float fa, float fb, const float* Wrow,
                                         ull* A0, ull* A1)
{
    ull ha = pk2(fa, fa), hb = pk2(fb, fb);
    const ulonglong2* wr = (const ulonglong2*)Wrow;
#pragma unroll
    for (int q = 0; q < 8; q++) {
        ulonglong2 wv = wr[q];
        A0[2 * q]     = ffma2(ha, wv.x, A0[2 * q]);
        A0[2 * q + 1] = ffma2(ha, wv.y, A0[2 * q + 1]);
        A1[2 * q]     = ffma2(hb, wv.x, A1[2 * q]);
        A1[2 * q + 1] = ffma2(hb, wv.y, A1[2 * q + 1]);
    }
}

// ---------------------------------------------------------------------------
// Kernel A: LSH bin assignment. one thread per token.
// ---------------------------------------------------------------------------
__global__ void k_bins(const float* __restrict__ xd,
                       const int* __restrict__ msk,
                       const float* __restrict__ codebook)
{
    __shared__ float cb[25 * 32];
    int tid = threadIdx.x;
    for (int e = tid; e < 25 * 32; e += 128) {
        int h = e >> 5, d = e & 31;
        cb[e] = codebook[d * 100 + h];
    }
    __syncthreads();

    int gid = blockIdx.x * 128 + tid;
    const float* xr = xd + (size_t)gid * DDIM;
    float x[32];
#pragma unroll
    for (int c = 0; c < 8; c++) {
        float4 v = ((const float4*)xr)[c];
        x[c * 4 + 0] = v.x; x[c * 4 + 1] = v.y; x[c * 4 + 2] = v.z; x[c * 4 + 3] = v.w;
    }
    float mul[25];
#pragma unroll
    for (int h = 0; h < 25; h++) {
        float a0 = 0.f, a1 = 0.f, a2 = 0.f, a3 = 0.f;
#pragma unroll
        for (int d = 0; d < 32; d += 4) {
            a0 += x[d + 0] * cb[h * 32 + d + 0];
            a1 += x[d + 1] * cb[h * 32 + d + 1];
            a2 += x[d + 2] * cb[h * 32 + d + 2];
            a3 += x[d + 3] * cb[h * 32 + d + 3];
        }
        mul[h] = (a0 + a1) + (a2 + a3);
    }
    float best = -INFINITY; int arg = 0;
#pragma unroll
    for (int h = 0; h < 25; h++)
        if (mul[h] > best) { best = mul[h]; arg = h; }
#pragma unroll
    for (int h = 0; h < 25; h++) {
        float v = -mul[h];
        if (v > best) { best = v; arg = 25 + h; }
    }
    g_bin_idx[gid] = arg + (msk[gid] != 0 ? 0 : (NBINS - 1));
}

// ---------------------------------------------------------------------------
// Kernel B: stable counting sort per batch -> bins_split
// ---------------------------------------------------------------------------
__global__ void k_sort(float* __restrict__ out)
{
    __shared__ unsigned short hist[128][NKEY];
    __shared__ int key_start[NKEY];
    __shared__ int total[NKEY];

    int t = threadIdx.x;
    int b = blockIdx.x;
    const int* keys = g_bin_idx + b * NTOK;

    for (int k = 0; k < NKEY; k++) hist[t][k] = 0;
    __syncthreads();

    int base = t * 50;
    for (int i = 0; i < 50; i++) hist[t][keys[base + i]]++;
    __syncthreads();

    if (t < NKEY) {
        int run = 0;
        for (int t2 = 0; t2 < 128; t2++) {
            int c = hist[t2][t];
            hist[t2][t] = (unsigned short)run;
            run += c;
        }
        total[t] = run;
    }
    __syncthreads();
    if (t == 0) {
        int s = 0;
        for (int k = 0; k < NKEY; k++) { key_start[k] = s; s += total[k]; }
    }
    __syncthreads();

    int*   ob = g_bins + b * NTOK;
    float* of = out + (size_t)b * NTOK;
    for (int i = 0; i < 50; i++) {
        int n = base + i;
        int k = keys[n];
        int pos = key_start[k] + (int)hist[t][k];
        hist[t][k]++;
        ob[pos] = n;
        of[pos] = (float)n;
    }
}

// ---------------------------------------------------------------------------
// Kernel D (fused): zero-fill | gather | compute(active x active pairs only)
// 128 threads, 3 CTA/SM.
// fill:    (tile, iq)  zero rows with mi==0 (full) or mj==0 (per-j row)
// gather:  x_features_binned + msk_f_binned copy
// compute: (tile, ig, jg) groups of 32 active slots; in-block compaction;
//          blocks beyond ceil(nAct/32) exit immediately. No mask multiplies.
// ---------------------------------------------------------------------------
__global__ void __launch_bounds__(128, 3) k_dm(
    const float* __restrict__ xd, const float* __restrict__ xf,
    const int* __restrict__ msk,
    const float* __restrict__ W1, const float* __restrict__ b1,
    const float* __restrict__ W2, const float* __restrict__ b2,
    const float* __restrict__ W3, const float* __restrict__ b3,
    float* __restrict__ out)
{
    extern __shared__ float sm[];
    int*   actS = (int*)sm;          // 128 (fill path reuses as mask array)
    int*   hdr  = (int*)(sm + 128);  // [0]=nAct, [1..4]=wcnt, [5..8]=woff
    float* W1s  = sm + 144;          // 2048
    float* W2s  = sm + 2192;         // 1024
    float* W3s  = sm + 3216;         // 1024
    float* b2s  = sm + 4240;         // 32
    float* b3s  = sm + 4272;         // 32
    float* XdS  = sm + 4304;         // 64*36 = 2304 (rows 0-31 i, 32-63 j)
    float* US   = sm + 6608;         // 32*36 = 1152
    float* VTS  = sm + 7760;         // 1024
    // total 8784 floats = 35136 B

    int tid = threadIdx.x;
    int blk = blockIdx.x;

    // ---------------- fill path: zero all masked dm rows ----------------
    if (blk < FILL_BLOCKS) {
        int tile = blk >> 2, iq = blk & 3;      // tile 0..99
        int b = tile / NBINS, bin = tile % NBINS;
        int rowt = g_bins[b * NTOK + bin * BINSZ + tid];
        actS[tid] = (msk[b * NTOK + rowt] != 0);
        __syncthreads();
        float4 z4 = make_float4(0.f, 0.f, 0.f, 0.f);
        float4* tbase = (float4*)(out + O2 + (size_t)tile * BINSZ * BINSZ * 32);
        int mj0 = actS[tid];           // this thread's j-slot mask
        for (int ii = 0; ii < 32; ii++) {
            int i = iq * 32 + ii;
            float4* rowp = tbase + (size_t)i * 1024;
            if (!actS[i]) {
#pragma unroll
                for (int e = 0; e < 8; e++) rowp[e * 128 + tid] = z4;
            } else if (!mj0) {
                float4* jp = rowp + tid * 8;
#pragma unroll
                for (int q = 0; q < 8; q++) jp[q] = z4;
            }
        }
        return;
    }

    // ---------------- gather path ----------------
    if (blk < COMP_BASE) {
        int g = blk - GATH_BASE;             // 0..199, 64 rows each
        if (tid < 64) {
            int gid = g * 64 + tid;
            int bb = gid / NTOK;
            int src = g_bins[gid];
            out[O3 + gid] = (msk[bb * NTOK + src] != 0) ? 1.f : 0.f;
        }
        int base = g * 64;
        float4* dst = (float4*)(out + O1);
#pragma unroll 4
        for (int p = 0; p < 32; p++) {
            int idx = p * 128 + tid;         // 0..4095
            int r = idx >> 6, c = idx & 63;
            int gid = base + r;
            int bb = gid / NTOK;
            int src = g_bins[gid];
            dst[(size_t)gid * 64 + c] =
                ((const float4*)(xf + ((size_t)(bb * NTOK + src)) * FDIM))[c];
        }
        return;
    }

    // ---------------- compute path ----------------
    int cb   = blk - COMP_BASE;
    int tile = cb >> 4;                  // 0..99
    int ig   = (cb >> 2) & 3;            // i slot-group
    int jg   = cb & 3;                   // j slot-group
    int b    = tile / NBINS;
    int bin  = tile % NBINS;
    int w    = tid >> 5, lane = tid & 31;
    int base = b * NTOK + bin * BINSZ;

    // in-block stable compaction of active slots
    int rowt = g_bins[base + tid];
    int m = (msk[b * NTOK + rowt] != 0);
    unsigned bal = __ballot_sync(0xffffffffu, m);
    if (lane == 0) hdr[1 + w] = __popc(bal);
    __syncthreads();
    if (tid == 0) {
        int off = 0;
#pragma unroll
        for (int q = 0; q < 4; q++) { hdr[5 + q] = off; off += hdr[1 + q]; }
        hdr[0] = off;
    }
    __syncthreads();
    int nAct = hdr[0];
    if (ig * 32 >= nAct || jg * 32 >= nAct) return;
    if (m) actS[hdr[5 + w] + __popc(bal & ((1u << lane) - 1u))] = tid;
    __syncthreads();

    int ni = min(32, nAct - ig * 32);
    int nj = min(32, nAct - jg * 32);

    // stage weights
    for (int e = tid; e < 2048; e += 128) W1s[e] = W1[e];
    for (int e = tid; e < 1024; e += 128) { W2s[e] = W2[e]; W3s[e] = W3[e]; }
    if (tid < 32) { b2s[tid] = b2[tid]; b3s[tid] = b3[tid]; }

    // gather 64 x_dist rows (clamped duplicate slots beyond ni/nj), stride 36
#pragma unroll
    for (int c = 0; c < 4; c++) {
        int idx = c * 128 + tid;             // 0..511
        int r = idx >> 3, q = idx & 7;
        int slot = (r < 32) ? actS[ig * 32 + min(r, ni - 1)]
                            : actS[jg * 32 + min(r - 32, nj - 1)];
        int trow = g_bins[base + slot];
        float4 v = ((const float4*)(xd + ((size_t)(b * NTOK + trow)) * DDIM))[q];
        *(float4*)(XdS + r * 36 + q * 4) = v;
    }
    __syncthreads();

    // U (32 i-local rows) and V^T[k][j] (32 j-local rows)
    {
        int r = tid >> 2, og = (tid & 3) * 8;
        float acc[8];
#pragma unroll
        for (int c = 0; c < 8; c++) acc[c] = b1[og + c];
#pragma unroll
        for (int d = 0; d < 32; d++) {
            float xv = XdS[r * 36 + d];
            const float* wr = W1s + d * 32 + og;
#pragma unroll
            for (int c = 0; c < 8; c++) acc[c] += xv * wr[c];
        }
        float* u = US + r * 36 + og;
#pragma unroll
        for (int c = 0; c < 8; c++) u[c] = acc[c];

        float av[8];
#pragma unroll
        for (int c = 0; c < 8; c++) av[c] = 0.f;
#pragma unroll
        for (int d = 0; d < 32; d++) {
            float xv = XdS[(32 + r) * 36 + d];
            const float* wr = W1s + (32 + d) * 32 + og;
#pragma unroll
            for (int c = 0; c < 8; c++) av[c] += xv * wr[c];
        }
#pragma unroll
        for (int c = 0; c < 8; c++) VTS[(og + c) * 32 + r] = av[c];
    }
    __syncthreads();

    const ulonglong2* b2v = (const ulonglong2*)b2s;
    const ulonglong2* b3v = (const ulonglong2*)b3s;
    int sj = actS[jg * 32 + min(lane, nj - 1)];
    bool jok = (lane < nj);

#pragma unroll 1
    for (int t = 0; t < 4; t++) {
        int li0 = w * 8 + 2 * t;
        if (li0 >= ni) break;
        int li1 = li0 + 1;
        bool st1 = (li1 < ni);
        int s0 = actS[ig * 32 + li0];
        int s1 = actS[ig * 32 + (st1 ? li1 : li0)];

        // ---- layer 2 with h1 streamed ----
        ull A0[16], A1[16];
#pragma unroll
        for (int q = 0; q < 8; q++) {
            ulonglong2 bb = b2v[q];
            A0[2 * q] = bb.x; A0[2 * q + 1] = bb.y;
            A1[2 * q] = bb.x; A1[2 * q + 1] = bb.y;
        }
        {
            const float4* U0 = (const float4*)(US + li0 * 36);
            const float4* U1 = (const float4*)(US + (st1 ? li1 : li0) * 36);
#pragma unroll
            for (int k4 = 0; k4 < 8; k4++) {
                float4 u0 = U0[k4];
                float4 u1 = U1[k4];
                int k = k4 * 4;
                float v0 = VTS[(k + 0) * 32 + lane];
                acc_step(eluf(u0.x + v0), eluf(u1.x + v0), W2s + (k + 0) * 32, A0, A1);
                float v1 = VTS[(k + 1) * 32 + lane];
                acc_step(eluf(u0.y + v1), eluf(u1.y + v1), W2s + (k + 1) * 32, A0, A1);
                float v2 = VTS[(k + 2) * 32 + lane];
                acc_step(eluf(u0.z + v2), eluf(u1.z + v2), W2s + (k + 2) * 32, A0, A1);
                float v3 = VTS[(k + 3) * 32 + lane];
                acc_step(eluf(u0.w + v3), eluf(u1.w + v3), W2s + (k + 3) * 32, A0, A1);
            }
        }

        // h2 = elu(acc)
        float h2a[32], h2b[32];
#pragma unroll
        for (int a = 0; a < 16; a++) {
            float2 f0 = upk2(A0[a]);
            float2 f1 = upk2(A1[a]);
            h2a[2 * a] = eluf(f0.x); h2a[2 * a + 1] = eluf(f0.y);
            h2b[2 * a] = eluf(f1.x); h2b[2 * a + 1] = eluf(f1.y);
        }

        // ---- layer 3 ----
#pragma unroll
        for (int q = 0; q < 8; q++) {
            ulonglong2 bb = b3v[q];
            A0[2 * q] = bb.x; A0[2 * q + 1] = bb.y;
            A1[2 * q] = bb.x; A1[2 * q + 1] = bb.y;
        }
#pragma unroll
        for (int k = 0; k < 32; k++)
            acc_step(h2a[k], h2b[k], W3s + k * 32, A0, A1);

        // stores: active pairs only, no mask factor
        if (jok) {
            float* rp0 = out + O2 +
                (((size_t)tile * BINSZ + s0) * BINSZ + sj) * 32;
            float4* o0 = (float4*)rp0;
#pragma unroll
            for (int e = 0; e < 8; e++) {
                float2 fa = upk2(A0[2 * e]);
                float2 fb = upk2(A0[2 * e + 1]);
                float4 r;
                r.x = eluf(fa.x); r.y = eluf(fa.y);
                r.z = eluf(fb.x); r.w = eluf(fb.y);
                o0[e] = r;
            }
            if (st1) {
                float* rp1 = out + O2 +
                    (((size_t)tile * BINSZ + s1) * BINSZ + sj) * 32;
                float4* o1 = (float4*)rp1;
#pragma unroll
                for (int e = 0; e < 8; e++) {
                    float2 ga = upk2(A1[2 * e]);
                    float2 gb = upk2(A1[2 * e + 1]);
                    float4 r1;
                    r1.x = eluf(ga.x); r1.y = eluf(ga.y);
                    r1.z = eluf(gb.x); r1.w = eluf(gb.y);
                    o1[e] = r1;
                }
            }
        }
    }
}

// ---------------------------------------------------------------------------
extern "C" void kernel_launch(void* const* d_in, const int* in_sizes, int n_in,
                              void* d_out, int out_size)
{
    const float* xd  = (const float*)d_in[0];
    const float* xf  = (const float*)d_in[1];
    const int*   mk  = (const int*)d_in[2];
    const float* cb  = (const float*)d_in[3];
    const float* W1  = (const float*)d_in[4];
    const float* b1  = (const float*)d_in[5];
    const float* W2  = (const float*)d_in[6];
    const float* b2  = (const float*)d_in[7];
    const float* W3  = (const float*)d_in[8];
    const float* b3  = (const float*)d_in[9];
    float* out = (float*)d_out;

    k_bins<<<100, 128>>>(xd, mk, cb);
    k_sort<<<BTCH, 128>>>(out);

    cudaFuncSetAttribute(k_dm, cudaFuncAttributeMaxDynamicSharedMemorySize, 35136);
    k_dm<<<TOTAL_BLOCKS, 128, 35136>>>(
        xd, xf, mk, W1, b1, W2, b2, W3, b3, out);
}

// round 11
// speedup vs baseline: 1.0035x; 1.0035x over previous
#include <cuda_runtime.h>
#include <math.h>

#define BTCH 2
#define NTOK 6400
#define NBINS 50
#define BINSZ 128
#define DDIM 32
#define FDIM 256
#define NKEY 100

// output packing (floats): [bins_split | x_features_binned | dm | msk_f_binned]
#define O1 12800ULL
#define O2 3289600ULL
#define O3 55718400ULL

// fused-kernel block layout: [compute 1600 | gather 200 | fill 400]
#define COMP_BLOCKS 1600
#define GATH_BASE   1600
#define FILL_BASE   1800
#define TOTAL_BLOCKS 2200

typedef unsigned long long ull;

__device__ int g_bin_idx[BTCH * NTOK];
__device__ int g_bins[BTCH * NTOK];

__device__ __forceinline__ float eluf(float x) {
    return fmaxf(x, 0.f) + (__expf(fminf(x, 0.f)) - 1.f);
}

__device__ __forceinline__ ull pk2(float lo, float hi) {
    ull r;
    asm("mov.b64 %0, {%1, %2};" : "=l"(r) : "f"(lo), "f"(hi));
    return r;
}
__device__ __forceinline__ ull ffma2(ull a, ull b, ull c) {
    ull d;
    asm("fma.rn.f32x2 %0, %1, %2, %3;" : "=l"(d) : "l"(a), "l"(b), "l"(c));
    return d;
}
__device__ __forceinline__ float2 upk2(ull a) {
    float2 v;
    asm("mov.b64 {%0, %1}, %2;" : "=f"(v.x), "=f"(v.y) : "l"(a));
    return v;
}

__device__ __forceinline__ void acc_step(float fa, float fb, const float* Wrow,
                                         ull* A0, ull* A1)
{
    ull ha = pk2(fa, fa), hb = pk2(fb, fb);
    const ulonglong2* wr = (const ulonglong2*)Wrow;
#pragma unroll
    for (int q = 0; q < 8; q++) {
        ulonglong2 wv = wr[q];
        A0[2 * q]     = ffma2(ha, wv.x, A0[2 * q]);
        A0[2 * q + 1] = ffma2(ha, wv.y, A0[2 * q + 1]);
        A1[2 * q]     = ffma2(hb, wv.x, A1[2 * q]);
        A1[2 * q + 1] = ffma2(hb, wv.y, A1[2 * q + 1]);
    }
}

// ---------------------------------------------------------------------------
// no-op launch to align ncu's skip-count onto k_dm
// ---------------------------------------------------------------------------
__global__ void k_nop() {}

// ---------------------------------------------------------------------------
// Kernel A: LSH bin assignment
// ---------------------------------------------------------------------------
__global__ void k_bins(const float* __restrict__ xd,
                       const int* __restrict__ msk,
                       const float* __restrict__ codebook)
{
    __shared__ float cb[25 * 32];
    int tid = threadIdx.x;
    for (int e = tid; e < 25 * 32; e += 128) {
        int h = e >> 5, d = e & 31;
        cb[e] = codebook[d * 100 + h];
    }
    __syncthreads();

    int gid = blockIdx.x * 128 + tid;
    const float* xr = xd + (size_t)gid * DDIM;
    float x[32];
#pragma unroll
    for (int c = 0; c < 8; c++) {
        float4 v = ((const float4*)xr)[c];
        x[c * 4 + 0] = v.x; x[c * 4 + 1] = v.y; x[c * 4 + 2] = v.z; x[c * 4 + 3] = v.w;
    }
    float mul[25];
#pragma unroll
    for (int h = 0; h < 25; h++) {
        float a0 = 0.f, a1 = 0.f, a2 = 0.f, a3 = 0.f;
#pragma unroll
        for (int d = 0; d < 32; d += 4) {
            a0 += x[d + 0] * cb[h * 32 + d + 0];
            a1 += x[d + 1] * cb[h * 32 + d + 1];
            a2 += x[d + 2] * cb[h * 32 + d + 2];
            a3 += x[d + 3] * cb[h * 32 + d + 3];
        }
        mul[h] = (a0 + a1) + (a2 + a3);
    }
    float best = -INFINITY; int arg = 0;
#pragma unroll
    for (int h = 0; h < 25; h++)
        if (mul[h] > best) { best = mul[h]; arg = h; }
#pragma unroll
    for (int h = 0; h < 25; h++) {
        float v = -mul[h];
        if (v > best) { best = v; arg = 25 + h; }
    }
    g_bin_idx[gid] = arg + (msk[gid] != 0 ? 0 : (NBINS - 1));
}

// ---------------------------------------------------------------------------
// Kernel B: stable counting sort per batch -> bins_split
// ---------------------------------------------------------------------------
__global__ void k_sort(float* __restrict__ out)
{
    __shared__ unsigned short hist[128][NKEY];
    __shared__ int key_start[NKEY];
    __shared__ int total[NKEY];

    int t = threadIdx.x;
    int b = blockIdx.x;
    const int* keys = g_bin_idx + b * NTOK;

    for (int k = 0; k < NKEY; k++) hist[t][k] = 0;
    __syncthreads();

    int base = t * 50;
    for (int i = 0; i < 50; i++) hist[t][keys[base + i]]++;
    __syncthreads();

    if (t < NKEY) {
        int run = 0;
        for (int t2 = 0; t2 < 128; t2++) {
            int c = hist[t2][t];
            hist[t2][t] = (unsigned short)run;
            run += c;
        }
        total[t] = run;
    }
    __syncthreads();
    if (t == 0) {
        int s = 0;
        for (int k = 0; k < NKEY; k++) { key_start[k] = s; s += total[k]; }
    }
    __syncthreads();

    int*   ob = g_bins + b * NTOK;
    float* of = out + (size_t)b * NTOK;
    for (int i = 0; i < 50; i++) {
        int n = base + i;
        int k = keys[n];
        int pos = key_start[k] + (int)hist[t][k];
        hist[t][k]++;
        ob[pos] = n;
        of[pos] = (float)n;
    }
}

// ---------------------------------------------------------------------------
// Kernel D (fused): compute(active x active) | gather | zero-fill
// All dm stores fully coalesced (128B rows written by whole warps).
// ---------------------------------------------------------------------------
__global__ void __launch_bounds__(128, 3) k_dm(
    const float* __restrict__ xd, const float* __restrict__ xf,
    const int* __restrict__ msk,
    const float* __restrict__ W1, const float* __restrict__ b1,
    const float* __restrict__ W2, const float* __restrict__ b2,
    const float* __restrict__ W3, const float* __restrict__ b3,
    float* __restrict__ out)
{
    extern __shared__ float sm[];
    int*   actS = (int*)sm;          // 128
    int*   hdr  = (int*)(sm + 128);  // 16
    float* W2s  = sm + 144;          // 1024
    float* W3s  = sm + 1168;         // 1024
    float* b2s  = sm + 2192;         // 32
    float* b3s  = sm + 2224;         // 32
    float* US   = sm + 2256;         // 32*36 = 1152
    float* VTS  = sm + 3408;         // 1024
    float* W1s  = sm + 4432;         // 2048  (dead after prologue)
    float* XdS  = sm + 6480;         // 64*36 = 2304 (dead after prologue)
    // stage region reuses W1s..XdS after prologue: 4 warps x 32x33 floats
    // total 8784 floats = 35136 B

    int tid = threadIdx.x;
    int blk = blockIdx.x;

    // ---------------- gather path ----------------
    if (blk >= GATH_BASE && blk < FILL_BASE) {
        int g = blk - GATH_BASE;             // 0..199, 64 rows each
        if (tid < 64) {
            int gid = g * 64 + tid;
            int bb = gid / NTOK;
            int src = g_bins[gid];
            out[O3 + gid] = (msk[bb * NTOK + src] != 0) ? 1.f : 0.f;
        }
        int base = g * 64;
        float4* dst = (float4*)(out + O1);
#pragma unroll 4
        for (int p = 0; p < 32; p++) {
            int idx = p * 128 + tid;         // 0..4095
            int r = idx >> 6, c = idx & 63;
            int gid = base + r;
            int bb = gid / NTOK;
            int src = g_bins[gid];
            dst[(size_t)gid * 64 + c] =
                ((const float4*)(xf + ((size_t)(bb * NTOK + src)) * FDIM))[c];
        }
        return;
    }

    // ---------------- fill path: zero all masked dm rows, coalesced -------
    if (blk >= FILL_BASE) {
        int fb = blk - FILL_BASE;
        int tile = fb >> 2, iq = fb & 3;     // tile 0..99
        int b = tile / NBINS, bin = tile % NBINS;
        int rowt = g_bins[b * NTOK + bin * BINSZ + tid];
        actS[tid] = (msk[b * NTOK + rowt] != 0);
        __syncthreads();
        int w = tid >> 5, lane = tid & 31;
        float4 z4 = make_float4(0.f, 0.f, 0.f, 0.f);
        float* tbase = out + O2 + (size_t)tile * BINSZ * BINSZ * 32;
        for (int ii = 0; ii < 32; ii++) {
            int i = iq * 32 + ii;
            float* rowp = tbase + (size_t)i * (BINSZ * 32);
            if (!actS[i]) {
                // whole i-row: 4096 floats, coalesced
                float4* rp = (float4*)rowp;
#pragma unroll
                for (int e = 0; e < 8; e++) rp[e * 128 + tid] = z4;
            } else {
                // zero inactive-j rows: one 128B row per warp-instruction
                for (int j = w; j < 128; j += 4)
                    if (!actS[j]) rowp[j * 32 + lane] = 0.f;
            }
        }
        return;
    }

    // ---------------- compute path ----------------
    int cb   = blk;
    int tile = cb >> 4;                  // 0..99
    int ig   = (cb >> 2) & 3;            // i slot-group
    int jg   = cb & 3;                   // j slot-group
    int b    = tile / NBINS;
    int bin  = tile % NBINS;
    int w    = tid >> 5, lane = tid & 31;
    int base = b * NTOK + bin * BINSZ;

    // in-block stable compaction of active slots
    int rowt = g_bins[base + tid];
    int m = (msk[b * NTOK + rowt] != 0);
    unsigned bal = __ballot_sync(0xffffffffu, m);
    if (lane == 0) hdr[1 + w] = __popc(bal);
    __syncthreads();
    if (tid == 0) {
        int off = 0;
#pragma unroll
        for (int q = 0; q < 4; q++) { hdr[5 + q] = off; off += hdr[1 + q]; }
        hdr[0] = off;
    }
    __syncthreads();
    int nAct = hdr[0];
    if (ig * 32 >= nAct || jg * 32 >= nAct) return;
    if (m) actS[hdr[5 + w] + __popc(bal & ((1u << lane) - 1u))] = tid;
    __syncthreads();

    int ni = min(32, nAct - ig * 32);
    int nj = min(32, nAct - jg * 32);

    // stage weights
    for (int e = tid; e < 2048; e += 128) W1s[e] = W1[e];
    for (int e = tid; e < 1024; e += 128) { W2s[e] = W2[e]; W3s[e] = W3[e]; }
    if (tid < 32) { b2s[tid] = b2[tid]; b3s[tid] = b3[tid]; }

    // gather 64 x_dist rows (clamped duplicates beyond ni/nj), stride 36
#pragma unroll
    for (int c = 0; c < 4; c++) {
        int idx = c * 128 + tid;             // 0..511
        int r = idx >> 3, q = idx & 7;
        int slot = (r < 32) ? actS[ig * 32 + min(r, ni - 1)]
                            : actS[jg * 32 + min(r - 32, nj - 1)];
        int trow = g_bins[base + slot];
        float4 v = ((const float4*)(xd + ((size_t)(b * NTOK + trow)) * DDIM))[q];
        *(float4*)(XdS + r * 36 + q * 4) = v;
    }
    __syncthreads();

    // U (32 i-local rows) and V^T[k][j] (32 j-local rows)
    {
        int r = tid >> 2, og = (tid & 3) * 8;
        float acc[8];
#pragma unroll
        for (int c = 0; c < 8; c++) acc[c] = b1[og + c];
#pragma unroll
        for (int d = 0; d < 32; d++) {
            float xv = XdS[r * 36 + d];
            const float* wr = W1s + d * 32 + og;
#pragma unroll
            for (int c = 0; c < 8; c++) acc[c] += xv * wr[c];
        }
        float* u = US + r * 36 + og;
#pragma unroll
        for (int c = 0; c < 8; c++) u[c] = acc[c];

        float av[8];
#pragma unroll
        for (int c = 0; c < 8; c++) av[c] = 0.f;
#pragma unroll
        for (int d = 0; d < 32; d++) {
            float xv = XdS[(32 + r) * 36 + d];
            const float* wr = W1s + (32 + d) * 32 + og;
#pragma unroll
            for (int c = 0; c < 8; c++) av[c] += xv * wr[c];
        }
#pragma unroll
        for (int c = 0; c < 8; c++) VTS[(og + c) * 32 + r] = av[c];
    }
    __syncthreads();
    // W1s/XdS now dead -> per-warp transpose stage (32x33 floats each)
    float* stg = sm + 4432 + w * 1056;

    const ulonglong2* b2v = (const ulonglong2*)b2s;
    const ulonglong2* b3v = (const ulonglong2*)b3s;
    // per-i output bases: row (tile, s, sj)*32 + lane
    float* outT = out + O2 + (size_t)tile * BINSZ * BINSZ * 32 + lane;

#pragma unroll 1
    for (int t = 0; t < 4; t++) {
        int li0 = w * 8 + 2 * t;
        if (li0 >= ni) break;
        int li1 = li0 + 1;
        bool st1 = (li1 < ni);
        int s0 = actS[ig * 32 + li0];
        int s1 = actS[ig * 32 + (st1 ? li1 : li0)];

        // ---- layer 2 with h1 streamed ----
        ull A0[16], A1[16];
#pragma unroll
        for (int q = 0; q < 8; q++) {
            ulonglong2 bb = b2v[q];
            A0[2 * q] = bb.x; A0[2 * q + 1] = bb.y;
            A1[2 * q] = bb.x; A1[2 * q + 1] = bb.y;
        }
        {
            const float4* U0 = (const float4*)(US + li0 * 36);
            const float4* U1 = (const float4*)(US + (st1 ? li1 : li0) * 36);
#pragma unroll
            for (int k4 = 0; k4 < 8; k4++) {
                float4 u0 = U0[k4];
                float4 u1 = U1[k4];
                int k = k4 * 4;
                float v0 = VTS[(k + 0) * 32 + lane];
                acc_step(eluf(u0.x + v0), eluf(u1.x + v0), W2s + (k + 0) * 32, A0, A1);
                float v1 = VTS[(k + 1) * 32 + lane];
                acc_step(eluf(u0.y + v1), eluf(u1.y + v1), W2s + (k + 1) * 32, A0, A1);
                float v2 = VTS[(k + 2) * 32 + lane];
                acc_step(eluf(u0.z + v2), eluf(u1.z + v2), W2s + (k + 2) * 32, A0, A1);
                float v3 = VTS[(k + 3) * 32 + lane];
                acc_step(eluf(u0.w + v3), eluf(u1.w + v3), W2s + (k + 3) * 32, A0, A1);
            }
        }

        // h2 = elu(acc)
        float h2a[32], h2b[32];
#pragma unroll
        for (int a = 0; a < 16; a++) {
            float2 f0 = upk2(A0[a]);
            float2 f1 = upk2(A1[a]);
            h2a[2 * a] = eluf(f0.x); h2a[2 * a + 1] = eluf(f0.y);
            h2b[2 * a] = eluf(f1.x); h2b[2 * a + 1] = eluf(f1.y);
        }

        // ---- layer 3 ----
#pragma unroll
        for (int q = 0; q < 8; q++) {
            ulonglong2 bb = b3v[q];
            A0[2 * q] = bb.x; A0[2 * q + 1] = bb.y;
            A1[2 * q] = bb.x; A1[2 * q + 1] = bb.y;
        }
#pragma unroll
        for (int k = 0; k < 32; k++)
            acc_step(h2a[k], h2b[k], W3s + k * 32, A0, A1);

        // ---- coalesced store via smem transpose, i0 then i1 ----
        // stage: stg[lane*33 + o] = final value (lane = j-local)
#pragma unroll
        for (int a = 0; a < 16; a++) {
            float2 f = upk2(A0[a]);
            stg[lane * 33 + 2 * a]     = eluf(f.x);
            stg[lane * 33 + 2 * a + 1] = eluf(f.y);
        }
        __syncwarp();
        {
            float* rT = outT + (size_t)s0 * (BINSZ * 32);
            for (int g = 0; g < nj; g++) {
                int sjg = actS[jg * 32 + g];
                rT[(size_t)sjg * 32] = stg[g * 33 + lane];
            }
        }
        __syncwarp();
        if (st1) {
#pragma unroll
            for (int a = 0; a < 16; a++) {
                float2 f = upk2(A1[a]);
                stg[lane * 33 + 2 * a]     = eluf(f.x);
                stg[lane * 33 + 2 * a + 1] = eluf(f.y);
            }
            __syncwarp();
            float* rT = outT + (size_t)s1 * (BINSZ * 32);
            for (int g = 0; g < nj; g++) {
                int sjg = actS[jg * 32 + g];
                rT[(size_t)sjg * 32] = stg[g * 33 + lane];
            }
            __syncwarp();
        }
    }
}

// ---------------------------------------------------------------------------
extern "C" void kernel_launch(void* const* d_in, const int* in_sizes, int n_in,
                              void* d_out, int out_size)
{
    const float* xd  = (const float*)d_in[0];
    const float* xf  = (const float*)d_in[1];
    const int*   mk  = (const int*)d_in[2];
    const float* cb  = (const float*)d_in[3];
    const float* W1  = (const float*)d_in[4];
    const float* b1  = (const float*)d_in[5];
    const float* W2  = (const float*)d_in[6];
    const float* b2  = (const float*)d_in[7];
    const float* W3  = (const float*)d_in[8];
    const float* b3  = (const float*)d_in[9];
    float* out = (float*)d_out;

    k_nop<<<1, 32>>>();   // aligns ncu skip-count so k_dm is captured
    k_bins<<<100, 128>>>(xd, mk, cb);
    k_sort<<<BTCH, 128>>>(out);

    cudaFuncSetAttribute(k_dm, cudaFuncAttributeMaxDynamicSharedMemorySize, 35136);
    k_dm<<<TOTAL_BLOCKS, 128, 35136>>>(
        xd, xf, mk, W1, b1, W2, b2, W3, b3, out);
}